// round 1
// baseline (speedup 1.0000x reference)
#include <cuda_runtime.h>
#include <cuda_bf16.h>
#include <cstdint>

#define BDIM 8192
#define INDIM 512
#define HDIM 512
#define NG 2048      // 4*H output columns (gate-interleaved)
#define KA 2048      // split-K: [x_hi | x_lo | hx_hi | hx_lo]

// Scratch (device globals: allocation-free rule)
__device__ __nv_bfloat16 g_A[(size_t)BDIM * KA];   // 32 MB
__device__ __nv_bfloat16 g_Bm[(size_t)NG * KA];    // 8 MB
__device__ __align__(16) float g_bias[NG];

// ---------------- prep: weights (sign, gate-interleaved, duplicated over split K) ----
__global__ void prep_w(const float* __restrict__ Wih, const float* __restrict__ Whh,
                       const float* __restrict__ bih, const float* __restrict__ bhh) {
    int idx = blockIdx.x * blockDim.x + threadIdx.x;   // over NG*512
    if (idx >= NG * 512) return;
    int n = idx >> 9, k = idx & 511;
    int g = n >> 2, r = n & 3;
    int row = r * HDIM + g;
    float wi = Wih[(size_t)row * INDIM + k];
    float wh = Whh[(size_t)row * HDIM + k];
    __nv_bfloat16 si = __float2bfloat16(wi > 0.f ? 1.f : (wi < 0.f ? -1.f : 0.f));
    __nv_bfloat16 sh = __float2bfloat16(wh > 0.f ? 1.f : (wh < 0.f ? -1.f : 0.f));
    size_t base = (size_t)n * KA;
    g_Bm[base + k]        = si;
    g_Bm[base + 512 + k]  = si;
    g_Bm[base + 1024 + k] = sh;
    g_Bm[base + 1536 + k] = sh;
    if (k == 0) g_bias[n] = bih[row] + bhh[row];
}

// ---------------- prep: activations (hi/lo bf16 split) ------------------------------
__global__ void prep_a(const float* __restrict__ x, const float* __restrict__ hx) {
    int idx = blockIdx.x * blockDim.x + threadIdx.x;   // over BDIM*512
    if (idx >= BDIM * 512) return;
    int b = idx >> 9, k = idx & 511;
    size_t base = (size_t)b * KA;
    float v = x[(size_t)b * INDIM + k];
    __nv_bfloat16 hi = __float2bfloat16(v);
    __nv_bfloat16 lo = __float2bfloat16(v - __bfloat162float(hi));
    g_A[base + k]       = hi;
    g_A[base + 512 + k] = lo;
    v = hx[(size_t)b * HDIM + k];
    hi = __float2bfloat16(v);
    lo = __float2bfloat16(v - __bfloat162float(hi));
    g_A[base + 1024 + k] = hi;
    g_A[base + 1536 + k] = lo;
}

// ---------------- fused GEMM + LSTM epilogue -----------------------------------------
// C[8192,2048] = A @ B^T (bf16, fp32 accum), tile 128x128x32, 256 threads (2x4 warps).
// smem: A/B double-buffered, stride 40 bf16 (80B) -> conflict-free ldmatrix.
#define SM_AB_STRIDE 40           // bf16 elems per k-row (32 + 8 pad)
#define SM_BUF_BYTES 10240        // 128*40*2
#define SMEM_BYTES   40960        // 4 buffers (A0 A1 B0 B1); epilogue reuses 33792B
#define C_STRIDE 132              // fp32 stride for epilogue tile (half: 64 rows)

__device__ __forceinline__ void ldsm_x4(uint32_t& r0, uint32_t& r1, uint32_t& r2, uint32_t& r3,
                                        uint32_t addr) {
    asm volatile("ldmatrix.sync.aligned.m8n8.x4.shared.b16 {%0,%1,%2,%3}, [%4];"
                 : "=r"(r0), "=r"(r1), "=r"(r2), "=r"(r3) : "r"(addr));
}

__device__ __forceinline__ void mma16816(float* d, const uint32_t* a, const uint32_t* b) {
    asm volatile(
        "mma.sync.aligned.m16n8k16.row.col.f32.bf16.bf16.f32 "
        "{%0,%1,%2,%3}, {%4,%5,%6,%7}, {%8,%9}, {%0,%1,%2,%3};"
        : "+f"(d[0]), "+f"(d[1]), "+f"(d[2]), "+f"(d[3])
        : "r"(a[0]), "r"(a[1]), "r"(a[2]), "r"(a[3]), "r"(b[0]), "r"(b[1]));
}

__global__ void __launch_bounds__(256, 1)
blstm_gemm(const float* __restrict__ cx, float* __restrict__ out) {
    extern __shared__ unsigned char smem[];
    const int tid  = threadIdx.x;
    const int lane = tid & 31;
    const int warp = tid >> 5;
    const int wm = warp & 1;       // 2 warps along M (64 rows each)
    const int wn = warp >> 1;      // 4 warps along N (32 cols each)
    const int rb = blockIdx.x;     // 64 row blocks
    const int cb = blockIdx.y;     // 16 col blocks

    const uint32_t sbase = (uint32_t)__cvta_generic_to_shared(smem);

    float acc[4][4][4];
#pragma unroll
    for (int i = 0; i < 4; i++)
#pragma unroll
        for (int j = 0; j < 4; j++)
#pragma unroll
            for (int r = 0; r < 4; r++) acc[i][j][r] = 0.f;

    const __nv_bfloat16* gA0 = g_A  + (size_t)(rb * 128) * KA;
    const __nv_bfloat16* gB0 = g_Bm + (size_t)(cb * 128) * KA;

    auto load_tile = [&](int kt, int buf) {
        const __nv_bfloat16* gA = gA0 + kt * 32;
        const __nv_bfloat16* gB = gB0 + kt * 32;
        uint32_t sA = sbase + buf * SM_BUF_BYTES;
        uint32_t sB = sbase + 2 * SM_BUF_BYTES + buf * SM_BUF_BYTES;
#pragma unroll
        for (int i = tid; i < 512; i += 256) {
            int row = i >> 2, ch = i & 3;
            uint32_t so = (uint32_t)(row * SM_AB_STRIDE + ch * 8) * 2;
            const void* ga = gA + (size_t)row * KA + ch * 8;
            const void* gb = gB + (size_t)row * KA + ch * 8;
            uint32_t sa = sA + so, sb = sB + so;
            asm volatile("cp.async.cg.shared.global [%0], [%1], 16;" :: "r"(sa), "l"(ga));
            asm volatile("cp.async.cg.shared.global [%0], [%1], 16;" :: "r"(sb), "l"(gb));
        }
        asm volatile("cp.async.commit_group;");
    };

    load_tile(0, 0);

    const int lrow16 = lane & 15;       // ldmatrix row within 16
    const int khalf  = (lane >> 4) * 8; // ldmatrix k-half offset

#pragma unroll 1
    for (int kt = 0; kt < KA / 32; kt++) {
        int buf = kt & 1;
        if (kt + 1 < KA / 32) {
            load_tile(kt + 1, (kt + 1) & 1);
            asm volatile("cp.async.wait_group 1;");
        } else {
            asm volatile("cp.async.wait_group 0;");
        }
        __syncthreads();

        uint32_t sA = sbase + buf * SM_BUF_BYTES;
        uint32_t sB = sbase + 2 * SM_BUF_BYTES + buf * SM_BUF_BYTES;

#pragma unroll
        for (int ks = 0; ks < 2; ks++) {
            uint32_t a[4][4], b[4][2];
#pragma unroll
            for (int mi = 0; mi < 4; mi++) {
                uint32_t addr = sA +
                    (uint32_t)(((wm * 64 + mi * 16 + lrow16) * SM_AB_STRIDE) + ks * 16 + khalf) * 2;
                ldsm_x4(a[mi][0], a[mi][1], a[mi][2], a[mi][3], addr);
            }
#pragma unroll
            for (int h = 0; h < 2; h++) {
                uint32_t r0, r1, r2, r3;
                uint32_t addr = sB +
                    (uint32_t)(((wn * 32 + h * 16 + lrow16) * SM_AB_STRIDE) + ks * 16 + khalf) * 2;
                ldsm_x4(r0, r1, r2, r3, addr);
                b[h * 2 + 0][0] = r0; b[h * 2 + 0][1] = r2;   // n rows 0-7 of this 16
                b[h * 2 + 1][0] = r1; b[h * 2 + 1][1] = r3;   // n rows 8-15
            }
#pragma unroll
            for (int mi = 0; mi < 4; mi++)
#pragma unroll
                for (int ni = 0; ni < 4; ni++)
                    mma16816(acc[mi][ni], a[mi], b[ni]);
        }
        __syncthreads();
    }

    // ---------------- fused LSTM epilogue (two half-tiles of 64 rows) ----------------
    float* Csm = (float*)smem;
    const int qrow = lane >> 2;
    const int qcol2 = 2 * (lane & 3);
#pragma unroll 1
    for (int p = 0; p < 2; p++) {
        __syncthreads();
        if (wm == p) {
#pragma unroll
            for (int mi = 0; mi < 4; mi++)
#pragma unroll
                for (int ni = 0; ni < 4; ni++) {
                    int row0 = mi * 16 + qrow;
                    int col = wn * 32 + ni * 8 + qcol2;
                    Csm[row0 * C_STRIDE + col]           = acc[mi][ni][0];
                    Csm[row0 * C_STRIDE + col + 1]       = acc[mi][ni][1];
                    Csm[(row0 + 8) * C_STRIDE + col]     = acc[mi][ni][2];
                    Csm[(row0 + 8) * C_STRIDE + col + 1] = acc[mi][ni][3];
                }
        }
        __syncthreads();
#pragma unroll
        for (int i = tid; i < 64 * 32; i += 256) {
            int lr = i >> 5, cq = i & 31;
            float4 v  = *(const float4*)&Csm[lr * C_STRIDE + cq * 4];
            float4 bs = *(const float4*)&g_bias[cb * 128 + cq * 4];
            int grow = rb * 128 + p * 64 + lr;
            int g = cb * 32 + cq;
            float ig = v.x + bs.x;
            float fg = v.y + bs.y;
            float cg = v.z + bs.z;
            float og = v.w + bs.w;
            float cprev = cx[(size_t)grow * HDIM + g];
            float si = 1.f / (1.f + __expf(-ig));
            float sf = 1.f / (1.f + __expf(-fg));
            float so = 1.f / (1.f + __expf(-og));
            float tc = tanhf(cg);
            float cy = sf * cprev + si * tc;
            float hy = so * tanhf(cy);
            out[(size_t)grow * HDIM + g] = hy;
            out[(size_t)BDIM * HDIM + (size_t)grow * HDIM + g] = cy;
        }
    }
}

// ---------------- launch ------------------------------------------------------------
extern "C" void kernel_launch(void* const* d_in, const int* in_sizes, int n_in,
                              void* d_out, int out_size) {
    const float* x   = (const float*)d_in[0];
    const float* hx  = (const float*)d_in[1];
    const float* cx  = (const float*)d_in[2];
    const float* Wih = (const float*)d_in[3];
    const float* Whh = (const float*)d_in[4];
    const float* bih = (const float*)d_in[5];
    const float* bhh = (const float*)d_in[6];
    float* out = (float*)d_out;

    prep_w<<<(NG * 512 + 255) / 256, 256>>>(Wih, Whh, bih, bhh);
    prep_a<<<(BDIM * 512 + 255) / 256, 256>>>(x, hx);
    dim3 grid(BDIM / 128, NG / 128);
    blstm_gemm<<<grid, 256, SMEM_BYTES>>>(cx, out);
}

// round 3
// speedup vs baseline: 2.0179x; 2.0179x over previous
#include <cuda_runtime.h>
#include <cuda_bf16.h>
#include <cstdint>

#define BDIM 8192
#define HDIM 512
#define NG   2048          // 4*H gate-interleaved output cols
#define KAT  2048          // A K: [x_hi | hx_hi | x_lo | hx_lo]
#define KBT  1024          // B K: [si | sh]
#define NSTAGE 16          // K chunks of 64 over KBT
#define STAGE_BYTES 98304  // A_hi 16K + A_lo 16K + B 64K
#define SMEM_TOTAL (1024 + 2 * STAGE_BYTES)
#define IDESC_256 0x08400490u   // f32 accum, bf16 x bf16, M=128, N=256

// Real tcgen05 code only on the arch-specific sm_103a/sm_100a cubin pass; the
// generic compute_103 PTX pass (forward-compat embed) gets a stub.
#if !defined(__CUDA_ARCH__) || defined(__CUDA_ARCH_FEAT_SM103_ALL) || defined(__CUDA_ARCH_FEAT_SM100_ALL)
#define TCGEN05_OK 1
#else
#define TCGEN05_OK 0
#endif

// scratch (device globals — allocation-free rule)
__device__ __nv_bfloat16 g_A[(size_t)BDIM * KAT];   // 32 MB
__device__ __nv_bfloat16 g_B[(size_t)NG * KBT];     // 4 MB
__device__ __align__(16) float g_bias[NG];

// ---------------- PTX helpers -------------------------------------------------------
__device__ __forceinline__ uint32_t smem_u32(const void* p) {
    return (uint32_t)__cvta_generic_to_shared(p);
}
__device__ __forceinline__ void mbar_init(uint32_t a, uint32_t cnt) {
    asm volatile("mbarrier.init.shared.b64 [%0], %1;" :: "r"(a), "r"(cnt) : "memory");
}
__device__ __forceinline__ void mbar_wait(uint32_t a, uint32_t parity) {
    uint32_t done;
    asm volatile("{\n\t.reg .pred p;\n\t"
                 "mbarrier.try_wait.parity.acquire.cta.shared::cta.b64 p, [%1], %2;\n\t"
                 "selp.b32 %0, 1, 0, p;\n\t}"
                 : "=r"(done) : "r"(a), "r"(parity) : "memory");
    if (!done) {
        asm volatile("{\n\t.reg .pred P1;\n\t"
                     "W_%=:\n\t"
                     "mbarrier.try_wait.parity.acquire.cta.shared::cta.b64 P1, [%0], %1, 0x989680;\n\t"
                     "@P1 bra.uni D_%=;\n\t"
                     "bra.uni W_%=;\n\t"
                     "D_%=:\n\t}" :: "r"(a), "r"(parity) : "memory");
    }
}
__device__ __forceinline__ void cp16(uint32_t saddr, const void* gaddr) {
    asm volatile("cp.async.cg.shared.global [%0], [%1], 16;" :: "r"(saddr), "l"(gaddr));
}
__device__ __forceinline__ uint64_t mk_desc(uint32_t addr) {
    // SW128, Blackwell version=1, SBO=64, LBO=1
    const uint64_t base = (uint64_t(2) << 61) | (uint64_t(1) << 46) |
                          (uint64_t(64) << 32) | (uint64_t(1) << 16);
    return base | ((uint64_t)(addr >> 4) & 0x3FFF);
}
#if TCGEN05_OK
__device__ __forceinline__ void mma_f16_ss(uint32_t d, uint64_t ad, uint64_t bd,
                                           uint32_t en) {
    asm volatile("{\n\t.reg .pred p;\n\tsetp.ne.u32 p, %4, 0;\n\t"
                 "tcgen05.mma.cta_group::1.kind::f16 [%0], %1, %2, %3, {%5,%5,%5,%5}, p;\n\t}"
                 :: "r"(d), "l"(ad), "l"(bd), "r"(IDESC_256), "r"(en), "r"(0u) : "memory");
}
__device__ __forceinline__ void tc_commit(uint32_t mbar) {
    asm volatile("tcgen05.commit.cta_group::1.mbarrier::arrive::one.shared::cluster.b64 [%0];"
                 :: "r"(mbar) : "memory");
}
#define TC_LD_X32(r, addr)                                                     \
    asm volatile("tcgen05.ld.sync.aligned.32x32b.x32.b32 "                     \
        "{%0,%1,%2,%3,%4,%5,%6,%7,%8,%9,%10,%11,%12,%13,%14,%15,"             \
        "%16,%17,%18,%19,%20,%21,%22,%23,%24,%25,%26,%27,%28,%29,%30,%31}, [%32];" \
        : "=r"((r)[0]),"=r"((r)[1]),"=r"((r)[2]),"=r"((r)[3]),                 \
          "=r"((r)[4]),"=r"((r)[5]),"=r"((r)[6]),"=r"((r)[7]),                 \
          "=r"((r)[8]),"=r"((r)[9]),"=r"((r)[10]),"=r"((r)[11]),               \
          "=r"((r)[12]),"=r"((r)[13]),"=r"((r)[14]),"=r"((r)[15]),             \
          "=r"((r)[16]),"=r"((r)[17]),"=r"((r)[18]),"=r"((r)[19]),             \
          "=r"((r)[20]),"=r"((r)[21]),"=r"((r)[22]),"=r"((r)[23]),             \
          "=r"((r)[24]),"=r"((r)[25]),"=r"((r)[26]),"=r"((r)[27]),             \
          "=r"((r)[28]),"=r"((r)[29]),"=r"((r)[30]),"=r"((r)[31])              \
        : "r"(addr))
#endif

// ---------------- prep: weights -----------------------------------------------------
__global__ void prep_w(const float* __restrict__ Wih, const float* __restrict__ Whh,
                       const float* __restrict__ bih, const float* __restrict__ bhh) {
    int idx = blockIdx.x * blockDim.x + threadIdx.x;    // NG * 128
    if (idx >= NG * 128) return;
    int n = idx >> 7, k4 = (idx & 127) * 4;
    int g = n >> 2, r = n & 3;
    int row = r * HDIM + g;
    float4 wi = *(const float4*)(Wih + (size_t)row * 512 + k4);
    float4 wh = *(const float4*)(Whh + (size_t)row * 512 + k4);
    __nv_bfloat16 si[4], sh[4];
    const float* pi = &wi.x; const float* ph = &wh.x;
#pragma unroll
    for (int j = 0; j < 4; j++) {
        si[j] = __float2bfloat16(pi[j] > 0.f ? 1.f : (pi[j] < 0.f ? -1.f : 0.f));
        sh[j] = __float2bfloat16(ph[j] > 0.f ? 1.f : (ph[j] < 0.f ? -1.f : 0.f));
    }
    size_t base = (size_t)n * KBT;
    *(uint2*)&g_B[base + k4]       = *(uint2*)si;
    *(uint2*)&g_B[base + 512 + k4] = *(uint2*)sh;
    if (k4 == 0) g_bias[n] = bih[row] + bhh[row];
}

// ---------------- prep: activations (hi/lo bf16 split) ------------------------------
__global__ void prep_a(const float* __restrict__ x, const float* __restrict__ hx) {
    int idx = blockIdx.x * blockDim.x + threadIdx.x;    // BDIM * 128
    if (idx >= BDIM * 128) return;
    int b = idx >> 7, k4 = (idx & 127) * 4;
    size_t base = (size_t)b * KAT;
    float4 vx = *(const float4*)(x + (size_t)b * 512 + k4);
    float4 vh = *(const float4*)(hx + (size_t)b * 512 + k4);
    __nv_bfloat16 xh[4], xl[4], hh[4], hl[4];
    const float* px = &vx.x; const float* pv = &vh.x;
#pragma unroll
    for (int j = 0; j < 4; j++) {
        xh[j] = __float2bfloat16(px[j]);
        xl[j] = __float2bfloat16(px[j] - __bfloat162float(xh[j]));
        hh[j] = __float2bfloat16(pv[j]);
        hl[j] = __float2bfloat16(pv[j] - __bfloat162float(hh[j]));
    }
    *(uint2*)&g_A[base + k4]        = *(uint2*)xh;
    *(uint2*)&g_A[base + 512 + k4]  = *(uint2*)hh;
    *(uint2*)&g_A[base + 1024 + k4] = *(uint2*)xl;
    *(uint2*)&g_A[base + 1536 + k4] = *(uint2*)hl;
}

// ---------------- tcgen05 GEMM + fused LSTM epilogue --------------------------------
// Tile: M=128 (rb), N=512 (cb). K: 16 stages of 64 (B); each stage runs A-hi and A-lo
// chunks against the same B chunk (B traffic halved). D: TMEM cols [0,512) fp32.
__global__ void __launch_bounds__(256, 1)
blstm_gemm(const float* __restrict__ cx, float* __restrict__ out) {
#if TCGEN05_OK
    extern __shared__ __align__(1024) unsigned char smem[];
    const int tid = threadIdx.x;
    const int lane = tid & 31, warp = tid >> 5;
    const int rb = blockIdx.x, cb = blockIdx.y;
    const uint32_t sbase = smem_u32(smem);
    const uint32_t mbar0 = sbase + 16, mbar1 = sbase + 24;

    if (tid == 0) { mbar_init(mbar0, 1); mbar_init(mbar1, 1); }
    if (warp == 0) {
        asm volatile("tcgen05.alloc.cta_group::1.sync.aligned.shared::cta.b32 [%0], %1;"
                     :: "r"(sbase), "r"(512u) : "memory");
    }
    __syncthreads();
    uint32_t tmem;
    asm volatile("ld.shared.b32 %0, [%1];" : "=r"(tmem) : "r"(sbase));

    const __nv_bfloat16* Abase = g_A + (size_t)(rb * 128) * KAT;
    const __nv_bfloat16* Bbase = g_B + (size_t)(cb * 512) * KBT;

    auto load_stage = [&](int kb) {
        uint32_t st = sbase + 1024 + (uint32_t)(kb & 1) * STAGE_BYTES;
#pragma unroll
        for (int it = 0; it < 8; it++) {            // A hi (1024) + A lo (1024) 16B chunks
            int i = tid + it * 256;
            int reg = i >> 10;                      // 0 = hi, 1 = lo
            int r = (i >> 3) & 127, c = i & 7;
            uint32_t off = (uint32_t)(r * 128 + c * 16);
            uint32_t sa = st + (uint32_t)reg * 16384 + (off ^ ((off >> 3) & 0x70));
            cp16(sa, Abase + (size_t)r * KAT + reg * 1024 + kb * 64 + c * 8);
        }
#pragma unroll
        for (int it = 0; it < 16; it++) {           // B (4096) 16B chunks
            int i = tid + it * 256;
            int r = i >> 3, c = i & 7;
            uint32_t off = (uint32_t)(r * 128 + c * 16);
            uint32_t sa = st + 32768u + (off ^ ((off >> 3) & 0x70));
            cp16(sa, Bbase + (size_t)r * KBT + kb * 64 + c * 8);
        }
        asm volatile("cp.async.commit_group;");
    };

    load_stage(0);
    int ph0 = 0, ph1 = 0;

#pragma unroll 1
    for (int s = 0; s < NSTAGE; s++) {
        const int buf = s & 1;
        if (s >= 1) {   // buffer for stage s+1 was used by mma(s-1)
            if (buf) { mbar_wait(mbar0, (uint32_t)ph0); ph0 ^= 1; }
            else     { mbar_wait(mbar1, (uint32_t)ph1); ph1 ^= 1; }
        }
        if (s + 1 < NSTAGE) {
            load_stage(s + 1);
            asm volatile("cp.async.wait_group 1;");
        } else {
            asm volatile("cp.async.wait_group 0;");
        }
        __syncthreads();
        if (tid == 0) {
            asm volatile("fence.proxy.async.shared::cta;" ::: "memory");
            uint32_t st = sbase + 1024 + (uint32_t)buf * STAGE_BYTES;
            uint64_t ah = mk_desc(st);
            uint64_t al = mk_desc(st + 16384);
            uint64_t b0 = mk_desc(st + 32768);
            uint64_t b1 = b0 + 2048;                // +32KB = N rows [256,512)
#pragma unroll
            for (int k = 0; k < 4; k++) {
                uint32_t en = (s == 0 && k == 0) ? 0u : 1u;
                mma_f16_ss(tmem,       ah + 2 * k, b0 + 2 * k, en);
                mma_f16_ss(tmem + 256, ah + 2 * k, b1 + 2 * k, en);
            }
#pragma unroll
            for (int k = 0; k < 4; k++) {
                mma_f16_ss(tmem,       al + 2 * k, b0 + 2 * k, 1u);
                mma_f16_ss(tmem + 256, al + 2 * k, b1 + 2 * k, 1u);
            }
            tc_commit(buf ? mbar1 : mbar0);
        }
    }
    // wait final MMA (stage 15 -> slot 1)
    mbar_wait(mbar1, (uint32_t)ph1);
    asm volatile("tcgen05.fence::after_thread_sync;" ::: "memory");

    // ---------------- fused LSTM epilogue: 8 chunks of 64 cols ----------------------
    float* Csm = (float*)(smem + 1024);             // 128 x 67 fp32
#pragma unroll 1
    for (int ch = 0; ch < 8; ch++) {
        if (ch) __syncthreads();
        if (warp < 4) {
            uint32_t r0[32], r1[32];
            TC_LD_X32(r0, tmem + ch * 64);
            TC_LD_X32(r1, tmem + ch * 64 + 32);
            asm volatile("tcgen05.wait::ld.sync.aligned;" ::: "memory");
            int row = warp * 32 + lane;
#pragma unroll
            for (int c = 0; c < 32; c++) {
                Csm[row * 67 + c]      = __uint_as_float(r0[c]);
                Csm[row * 67 + 32 + c] = __uint_as_float(r1[c]);
            }
        }
        __syncthreads();
        int row = tid >> 1, up = tid & 1;
        int grow = rb * 128 + row;
        int gu = cb * 128 + ch * 16 + up * 8;       // 8 hidden units per thread
        float4 cx0 = *(const float4*)(cx + (size_t)grow * HDIM + gu);
        float4 cx1 = *(const float4*)(cx + (size_t)grow * HDIM + gu + 4);
        float cprev[8] = {cx0.x, cx0.y, cx0.z, cx0.w, cx1.x, cx1.y, cx1.z, cx1.w};
        float hy[8], cy[8];
        const float* bsm = &Csm[row * 67 + up * 32];
        const float* bias = &g_bias[cb * 512 + ch * 64 + up * 32];
#pragma unroll
        for (int j = 0; j < 8; j++) {
            float ig = bsm[j * 4 + 0] + bias[j * 4 + 0];
            float fg = bsm[j * 4 + 1] + bias[j * 4 + 1];
            float cg = bsm[j * 4 + 2] + bias[j * 4 + 2];
            float og = bsm[j * 4 + 3] + bias[j * 4 + 3];
            float si = 1.f / (1.f + __expf(-ig));
            float sf = 1.f / (1.f + __expf(-fg));
            float so = 1.f / (1.f + __expf(-og));
            float tc = 2.f / (1.f + __expf(-2.f * cg)) - 1.f;
            float c = sf * cprev[j] + si * tc;
            cy[j] = c;
            hy[j] = so * (2.f / (1.f + __expf(-2.f * c)) - 1.f);
        }
        float* oh = out + (size_t)grow * HDIM + gu;
        float* oc = out + (size_t)BDIM * HDIM + (size_t)grow * HDIM + gu;
        *(float4*)oh       = make_float4(hy[0], hy[1], hy[2], hy[3]);
        *(float4*)(oh + 4) = make_float4(hy[4], hy[5], hy[6], hy[7]);
        *(float4*)oc       = make_float4(cy[0], cy[1], cy[2], cy[3]);
        *(float4*)(oc + 4) = make_float4(cy[4], cy[5], cy[6], cy[7]);
    }

    __syncthreads();
    if (warp == 0) {
        asm volatile("tcgen05.relinquish_alloc_permit.cta_group::1.sync.aligned;");
        asm volatile("tcgen05.dealloc.cta_group::1.sync.aligned.b32 %0, %1;"
                     :: "r"(tmem), "r"(512u));
    }
#endif  // TCGEN05_OK
}

// ---------------- launch ------------------------------------------------------------
extern "C" void kernel_launch(void* const* d_in, const int* in_sizes, int n_in,
                              void* d_out, int out_size) {
    const float* x   = (const float*)d_in[0];
    const float* hx  = (const float*)d_in[1];
    const float* cx  = (const float*)d_in[2];
    const float* Wih = (const float*)d_in[3];
    const float* Whh = (const float*)d_in[4];
    const float* bih = (const float*)d_in[5];
    const float* bhh = (const float*)d_in[6];
    float* out = (float*)d_out;

    cudaFuncSetAttribute(blstm_gemm, cudaFuncAttributeMaxDynamicSharedMemorySize,
                         SMEM_TOTAL);
    prep_w<<<(NG * 128 + 255) / 256, 256>>>(Wih, Whh, bih, bhh);
    prep_a<<<(BDIM * 128 + 255) / 256, 256>>>(x, hx);
    dim3 grid(BDIM / 128, NG / 512);
    blstm_gemm<<<grid, 256, SMEM_TOTAL>>>(cx, out);
}

// round 4
// speedup vs baseline: 2.2459x; 1.1130x over previous
#include <cuda_runtime.h>
#include <cuda_bf16.h>
#include <cstdint>

#define BDIM 8192
#define HDIM 512
#define NG   2048           // 4*H gate-interleaved output cols
#define NSTAGE 16           // K stages of 64 (B-K = 1024)
#define A_TILE 32768        // per (rb,kb): hi 16KB + lo 16KB, pre-swizzled
#define B_TILE 65536        // per (cb,kb): 512 rows x 128B, pre-swizzled
#define STAGE_BYTES (A_TILE + B_TILE)
#define SMEM_TOTAL (1024 + 2 * STAGE_BYTES)
#define IDESC_256 0x08400490u   // f32 accum, bf16 x bf16, M=128, N=256

#if !defined(__CUDA_ARCH__) || defined(__CUDA_ARCH_FEAT_SM103_ALL) || defined(__CUDA_ARCH_FEAT_SM100_ALL)
#define TCGEN05_OK 1
#else
#define TCGEN05_OK 0
#endif

// scratch (device globals — allocation-free rule). Tiled + pre-swizzled.
__device__ __align__(1024) unsigned char g_Atile[(size_t)64 * 16 * A_TILE];  // 32 MB
__device__ __align__(1024) unsigned char g_Btile[(size_t)4 * 16 * B_TILE];   // 4 MB
__device__ __align__(16) float g_bias[NG];

// ---------------- PTX helpers -------------------------------------------------------
__device__ __forceinline__ uint32_t smem_u32(const void* p) {
    return (uint32_t)__cvta_generic_to_shared(p);
}
__device__ __forceinline__ void mbar_init(uint32_t a, uint32_t cnt) {
    asm volatile("mbarrier.init.shared.b64 [%0], %1;" :: "r"(a), "r"(cnt) : "memory");
}
__device__ __forceinline__ void mbar_wait(uint32_t a, uint32_t parity) {
    uint32_t done;
    asm volatile("{\n\t.reg .pred p;\n\t"
                 "mbarrier.try_wait.parity.acquire.cta.shared::cta.b64 p, [%1], %2;\n\t"
                 "selp.b32 %0, 1, 0, p;\n\t}"
                 : "=r"(done) : "r"(a), "r"(parity) : "memory");
    if (!done) {
        asm volatile("{\n\t.reg .pred P1;\n\t"
                     "W_%=:\n\t"
                     "mbarrier.try_wait.parity.acquire.cta.shared::cta.b64 P1, [%0], %1, 0x989680;\n\t"
                     "@P1 bra.uni D_%=;\n\t"
                     "bra.uni W_%=;\n\t"
                     "D_%=:\n\t}" :: "r"(a), "r"(parity) : "memory");
    }
}
__device__ __forceinline__ void mbar_expect_tx(uint32_t a, uint32_t bytes) {
    asm volatile("mbarrier.arrive.expect_tx.shared.b64 _, [%0], %1;"
                 :: "r"(a), "r"(bytes) : "memory");
}
__device__ __forceinline__ void bulk_g2s(uint32_t dst, const void* src, uint32_t bytes,
                                         uint32_t mbar) {
    asm volatile("cp.async.bulk.shared::cta.global.mbarrier::complete_tx::bytes "
                 "[%0], [%1], %2, [%3];"
                 :: "r"(dst), "l"(src), "r"(bytes), "r"(mbar) : "memory");
}
__device__ __forceinline__ uint64_t mk_desc(uint32_t addr) {
    // SW128, Blackwell version=1, SBO=64, LBO=1
    const uint64_t base = (uint64_t(2) << 61) | (uint64_t(1) << 46) |
                          (uint64_t(64) << 32) | (uint64_t(1) << 16);
    return base | ((uint64_t)(addr >> 4) & 0x3FFF);
}
#if TCGEN05_OK
__device__ __forceinline__ void mma_f16_ss(uint32_t d, uint64_t ad, uint64_t bd,
                                           uint32_t en) {
    asm volatile("{\n\t.reg .pred p;\n\tsetp.ne.u32 p, %4, 0;\n\t"
                 "tcgen05.mma.cta_group::1.kind::f16 [%0], %1, %2, %3, {%5,%5,%5,%5}, p;\n\t}"
                 :: "r"(d), "l"(ad), "l"(bd), "r"(IDESC_256), "r"(en), "r"(0u) : "memory");
}
__device__ __forceinline__ void tc_commit(uint32_t mbar) {
    asm volatile("tcgen05.commit.cta_group::1.mbarrier::arrive::one.shared::cluster.b64 [%0];"
                 :: "r"(mbar) : "memory");
}
#define TC_LD_X32(r, addr)                                                     \
    asm volatile("tcgen05.ld.sync.aligned.32x32b.x32.b32 "                     \
        "{%0,%1,%2,%3,%4,%5,%6,%7,%8,%9,%10,%11,%12,%13,%14,%15,"             \
        "%16,%17,%18,%19,%20,%21,%22,%23,%24,%25,%26,%27,%28,%29,%30,%31}, [%32];" \
        : "=r"((r)[0]),"=r"((r)[1]),"=r"((r)[2]),"=r"((r)[3]),                 \
          "=r"((r)[4]),"=r"((r)[5]),"=r"((r)[6]),"=r"((r)[7]),                 \
          "=r"((r)[8]),"=r"((r)[9]),"=r"((r)[10]),"=r"((r)[11]),               \
          "=r"((r)[12]),"=r"((r)[13]),"=r"((r)[14]),"=r"((r)[15]),             \
          "=r"((r)[16]),"=r"((r)[17]),"=r"((r)[18]),"=r"((r)[19]),             \
          "=r"((r)[20]),"=r"((r)[21]),"=r"((r)[22]),"=r"((r)[23]),             \
          "=r"((r)[24]),"=r"((r)[25]),"=r"((r)[26]),"=r"((r)[27]),             \
          "=r"((r)[28]),"=r"((r)[29]),"=r"((r)[30]),"=r"((r)[31])              \
        : "r"(addr))
#endif

// ---------------- prep: weights -> g_Btile (signed, gate-interleaved, swizzled) ------
__global__ void prep_w(const float* __restrict__ Wih, const float* __restrict__ Whh,
                       const float* __restrict__ bih, const float* __restrict__ bhh) {
    int idx = blockIdx.x * blockDim.x + threadIdx.x;    // NG * 128
    if (idx >= NG * 128) return;
    int n = idx >> 7, k4 = (idx & 127) * 4;
    int g = n >> 2, r = n & 3;
    int row_w = r * HDIM + g;                           // source weight row
    int cb = n >> 9, row = n & 511;                     // tile coords
    int kb = k4 >> 6, col = k4 & 63;
    float4 wi = *(const float4*)(Wih + (size_t)row_w * 512 + k4);
    float4 wh = *(const float4*)(Whh + (size_t)row_w * 512 + k4);
    __nv_bfloat16 si[4], sh[4];
    const float* pi = &wi.x; const float* ph = &wh.x;
#pragma unroll
    for (int j = 0; j < 4; j++) {
        si[j] = __float2bfloat16(pi[j] > 0.f ? 1.f : (pi[j] < 0.f ? -1.f : 0.f));
        sh[j] = __float2bfloat16(ph[j] > 0.f ? 1.f : (ph[j] < 0.f ? -1.f : 0.f));
    }
    uint32_t inner = (uint32_t)(row * 128 + col * 2);
    uint32_t sw = inner ^ ((inner >> 3) & 0x70);
    unsigned char* base = g_Btile + (size_t)cb * 16 * B_TILE;
    *(uint2*)(base + (size_t)kb * B_TILE + sw)       = *(uint2*)si;  // K block [0,512)
    *(uint2*)(base + (size_t)(8 + kb) * B_TILE + sw) = *(uint2*)sh;  // K block [512,1024)
    if (k4 == 0) g_bias[n] = bih[row_w] + bhh[row_w];
}

// ---------------- prep: activations -> g_Atile (hi/lo bf16 split, swizzled) ----------
__global__ void prep_a(const float* __restrict__ x, const float* __restrict__ hx) {
    int idx = blockIdx.x * blockDim.x + threadIdx.x;    // BDIM * 128
    if (idx >= BDIM * 128) return;
    int b = idx >> 7, k4 = (idx & 127) * 4;
    int rb = b >> 7, row = b & 127;
    int kb = k4 >> 6, col = k4 & 63;
    float4 vx = *(const float4*)(x + (size_t)b * 512 + k4);
    float4 vh = *(const float4*)(hx + (size_t)b * 512 + k4);
    __nv_bfloat16 xh[4], xl[4], hh[4], hl[4];
    const float* px = &vx.x; const float* pv = &vh.x;
#pragma unroll
    for (int j = 0; j < 4; j++) {
        xh[j] = __float2bfloat16(px[j]);
        xl[j] = __float2bfloat16(px[j] - __bfloat162float(xh[j]));
        hh[j] = __float2bfloat16(pv[j]);
        hl[j] = __float2bfloat16(pv[j] - __bfloat162float(hh[j]));
    }
    uint32_t inner = (uint32_t)(row * 128 + col * 2);
    uint32_t sw = inner ^ ((inner >> 3) & 0x70);
    unsigned char* base = g_Atile + (size_t)rb * 16 * A_TILE;
    // x: K block kb (hi) / kb (lo half);  hx: K block 8+kb
    *(uint2*)(base + (size_t)kb * A_TILE + sw)                 = *(uint2*)xh;
    *(uint2*)(base + (size_t)kb * A_TILE + 16384 + sw)         = *(uint2*)xl;
    *(uint2*)(base + (size_t)(8 + kb) * A_TILE + sw)           = *(uint2*)hh;
    *(uint2*)(base + (size_t)(8 + kb) * A_TILE + 16384 + sw)   = *(uint2*)hl;
}

// ---------------- tcgen05 GEMM + fused LSTM epilogue --------------------------------
// Tile M=128, N=512. 16 K-stages of 64; bulk-async loads (2 UBLKCP per stage),
// warp-specialized: tid0 issues MMAs, tid32 issues loads.
__global__ void __launch_bounds__(256, 1)
blstm_gemm(const float* __restrict__ cx, float* __restrict__ out) {
#if TCGEN05_OK
    extern __shared__ __align__(1024) unsigned char smem[];
    const int tid = threadIdx.x;
    const int lane = tid & 31, warp = tid >> 5;
    const int rb = blockIdx.x, cb = blockIdx.y;
    const uint32_t sbase = smem_u32(smem);
    const uint32_t ldmbar[2]  = {sbase + 16, sbase + 24};
    const uint32_t mmambar[2] = {sbase + 32, sbase + 40};
    const uint32_t finmbar    = sbase + 48;

    if (tid == 0) {
        mbar_init(ldmbar[0], 1);  mbar_init(ldmbar[1], 1);
        mbar_init(mmambar[0], 1); mbar_init(mmambar[1], 1);
        mbar_init(finmbar, 1);
    }
    if (warp == 0) {
        asm volatile("tcgen05.alloc.cta_group::1.sync.aligned.shared::cta.b32 [%0], %1;"
                     :: "r"(sbase), "r"(512u) : "memory");
    }
    __syncthreads();
    uint32_t tmem;
    asm volatile("ld.shared.b32 %0, [%1];" : "=r"(tmem) : "r"(sbase));

    const unsigned char* Asrc0 = g_Atile + (size_t)rb * 16 * A_TILE;
    const unsigned char* Bsrc0 = g_Btile + (size_t)cb * 16 * B_TILE;

    if (tid == 32) {
        // ---- load issuer ----
        auto issue_load = [&](int s) {
            int buf = s & 1;
            uint32_t st = sbase + 1024 + (uint32_t)buf * STAGE_BYTES;
            mbar_expect_tx(ldmbar[buf], STAGE_BYTES);
            bulk_g2s(st,          Asrc0 + (size_t)s * A_TILE, A_TILE, ldmbar[buf]);
            bulk_g2s(st + A_TILE, Bsrc0 + (size_t)s * B_TILE, B_TILE, ldmbar[buf]);
        };
        issue_load(0);
        issue_load(1);
        int mph[2] = {0, 0};
#pragma unroll 1
        for (int s = 0; s + 2 < NSTAGE; s++) {
            int m = s & 1;
            mbar_wait(mmambar[m], (uint32_t)mph[m]);   // MMA(s) done -> buffer free
            mph[m] ^= 1;
            issue_load(s + 2);
        }
    } else if (tid == 0) {
        // ---- MMA issuer ----
        int lph[2] = {0, 0};
#pragma unroll 1
        for (int s = 0; s < NSTAGE; s++) {
            int buf = s & 1;
            mbar_wait(ldmbar[buf], (uint32_t)lph[buf]);
            lph[buf] ^= 1;
            uint32_t st = sbase + 1024 + (uint32_t)buf * STAGE_BYTES;
            uint64_t ah = mk_desc(st);                  // A hi
            uint64_t al = mk_desc(st + 16384);          // A lo
            uint64_t b0 = mk_desc(st + A_TILE);         // B rows [0,256)
            uint64_t b1 = b0 + 2048;                    // B rows [256,512)
#pragma unroll
            for (int k = 0; k < 4; k++) {
                uint32_t en = (s == 0 && k == 0) ? 0u : 1u;
                mma_f16_ss(tmem,       ah + 2 * k, b0 + 2 * k, en);
                mma_f16_ss(tmem + 256, ah + 2 * k, b1 + 2 * k, en);
            }
#pragma unroll
            for (int k = 0; k < 4; k++) {
                mma_f16_ss(tmem,       al + 2 * k, b0 + 2 * k, 1u);
                mma_f16_ss(tmem + 256, al + 2 * k, b1 + 2 * k, 1u);
            }
            tc_commit(mmambar[buf]);
            if (s == NSTAGE - 1) tc_commit(finmbar);    // all MMAs done signal
        }
    }

    // ---- all threads: wait for final MMA completion (single-phase barrier) ----
    mbar_wait(finmbar, 0u);
    asm volatile("tcgen05.fence::after_thread_sync;" ::: "memory");

    // ---- register-direct LSTM epilogue: 8 chunks x 32 cols per warp ----
    const int half = warp >> 2;            // warpgroup: col half
    const int sp   = warp & 3;             // TMEM subpartition
    const int row  = sp * 32 + lane;       // M row within tile
    const int grow = rb * 128 + row;
#pragma unroll 1
    for (int ch = 0; ch < 8; ch++) {
        uint32_t r[32];
        TC_LD_X32(r, tmem + ch * 64 + half * 32);
        asm volatile("tcgen05.wait::ld.sync.aligned;" ::: "memory");
        int gu = cb * 128 + ch * 16 + half * 8;         // first of 8 hidden units
        float4 cx0 = *(const float4*)(cx + (size_t)grow * HDIM + gu);
        float4 cx1 = *(const float4*)(cx + (size_t)grow * HDIM + gu + 4);
        float cprev[8] = {cx0.x, cx0.y, cx0.z, cx0.w, cx1.x, cx1.y, cx1.z, cx1.w};
        const float4* bias4 = (const float4*)&g_bias[cb * 512 + ch * 64 + half * 32];
        float hy[8], cy[8];
#pragma unroll
        for (int j = 0; j < 8; j++) {
            float4 bs = bias4[j];
            float ig = __uint_as_float(r[j * 4 + 0]) + bs.x;
            float fg = __uint_as_float(r[j * 4 + 1]) + bs.y;
            float cg = __uint_as_float(r[j * 4 + 2]) + bs.z;
            float og = __uint_as_float(r[j * 4 + 3]) + bs.w;
            float si = 1.f / (1.f + __expf(-ig));
            float sf = 1.f / (1.f + __expf(-fg));
            float so = 1.f / (1.f + __expf(-og));
            float tc = 2.f / (1.f + __expf(-2.f * cg)) - 1.f;
            float c = sf * cprev[j] + si * tc;
            cy[j] = c;
            hy[j] = so * (2.f / (1.f + __expf(-2.f * c)) - 1.f);
        }
        float* oh = out + (size_t)grow * HDIM + gu;
        float* oc = out + (size_t)BDIM * HDIM + (size_t)grow * HDIM + gu;
        *(float4*)oh       = make_float4(hy[0], hy[1], hy[2], hy[3]);
        *(float4*)(oh + 4) = make_float4(hy[4], hy[5], hy[6], hy[7]);
        *(float4*)oc       = make_float4(cy[0], cy[1], cy[2], cy[3]);
        *(float4*)(oc + 4) = make_float4(cy[4], cy[5], cy[6], cy[7]);
    }

    __syncthreads();
    if (warp == 0) {
        asm volatile("tcgen05.relinquish_alloc_permit.cta_group::1.sync.aligned;");
        asm volatile("tcgen05.dealloc.cta_group::1.sync.aligned.b32 %0, %1;"
                     :: "r"(tmem), "r"(512u));
    }
#endif  // TCGEN05_OK
}

// ---------------- launch ------------------------------------------------------------
extern "C" void kernel_launch(void* const* d_in, const int* in_sizes, int n_in,
                              void* d_out, int out_size) {
    const float* x   = (const float*)d_in[0];
    const float* hx  = (const float*)d_in[1];
    const float* cx  = (const float*)d_in[2];
    const float* Wih = (const float*)d_in[3];
    const float* Whh = (const float*)d_in[4];
    const float* bih = (const float*)d_in[5];
    const float* bhh = (const float*)d_in[6];
    float* out = (float*)d_out;

    cudaFuncSetAttribute(blstm_gemm, cudaFuncAttributeMaxDynamicSharedMemorySize,
                         SMEM_TOTAL);
    prep_w<<<(NG * 128 + 255) / 256, 256>>>(Wih, Whh, bih, bhh);
    prep_a<<<(BDIM * 128 + 255) / 256, 256>>>(x, hx);
    dim3 grid(BDIM / 128, NG / 512);
    blstm_gemm<<<grid, 256, SMEM_TOTAL>>>(cx, out);
}